// round 6
// baseline (speedup 1.0000x reference)
#include <cuda_runtime.h>
#include <cmath>
#include <cstring>
#include <vector>
#include <complex>
#include <algorithm>
#include <numeric>

#define NAO      14
#define NAO2     196
#define SPB      64            // samples per block
#define XST      65            // xs/os word stride (odd -> conflict-free columns)
#define NTHR     512
#define NWARP    16
#define TABCAP   2312          // param-struct capacity (dense worst case + pad)
#define TABSM    1536          // smem table capacity (fast path)
#define SMEM_FAST (2 * NAO2 * XST * 4 + TABSM * 8)
#define SMEM_FALL (2 * NAO2 * XST * 4)

// ---------------------------------------------------------------------------
// term[t] = { coef as float bits, column byte-offset (col * XST * 4) }
// Rows are sorted by term count (desc); terms stored contiguously per sorted
// row. tstart[i] / tstart[i+1] bound sorted-row i; rowoff[i] = rowid * XST.
// ---------------------------------------------------------------------------
struct Params2 {
    int2 term[TABCAP];
    int  tstart[200];
    int  rowoff[196];
    int  ntab;
};

__device__ __forceinline__ void stage_in(const float* __restrict__ x,
                                         float* xs, int n0, int npair, int tid)
{
    const float2* src = (const float2*)(x + (long long)n0 * NAO2);
    int s = tid / 98, e2 = tid - s * 98;
    #pragma unroll 2
    for (int f = tid; f < npair; f += NTHR) {
        float2 v = src[f];
        int w = (2 * e2) * XST + s;
        xs[w]       = v.x;
        xs[w + XST] = v.y;
        e2 += 22; s += 5;
        if (e2 >= 98) { e2 -= 98; s += 1; }
    }
}

__device__ __forceinline__ void stage_out(float* __restrict__ out,
                                          const float* os, int n0, int npair, int tid)
{
    float2* dst = (float2*)(out + (long long)n0 * NAO2);
    int s = tid / 98, e2 = tid - s * 98;
    #pragma unroll 2
    for (int f = tid; f < npair; f += NTHR) {
        int w = (2 * e2) * XST + s;
        float2 v;
        v.x = os[w];
        v.y = os[w + XST];
        dst[f] = v;
        e2 += 22; s += 5;
        if (e2 >= 98) { e2 -= 98; s += 1; }
    }
}

// ---------------- fast path: term table staged in shared memory ------------
__global__ void __launch_bounds__(NTHR, 2)
te_fast(const float* __restrict__ x, float* __restrict__ out, int nsamp,
        const __grid_constant__ Params2 P)
{
    extern __shared__ float sm[];
    float* xs  = sm;                         // [196][65]
    float* os  = sm + NAO2 * XST;            // [196][65]
    int2*  tbl = (int2*)(sm + 2 * NAO2 * XST);

    const int tid = threadIdx.x;
    for (int i = tid; i < P.ntab; i += NTHR) tbl[i] = P.term[i];

    const int n0 = blockIdx.x * SPB;
    int valid = nsamp - n0; if (valid > SPB) valid = SPB;
    const int npair = valid * (NAO2 / 2);

    stage_in(x, xs, n0, npair, tid);
    __syncthreads();

    const int wid  = tid >> 5;
    const int lane = tid & 31;
    const char* xl = (const char*)(xs + lane);

    for (int i = wid; i < NAO2; i += NWARP) {
        int t  = P.tstart[i];
        const int t1 = P.tstart[i + 1];
        const int ro = P.rowoff[i];
        float a0 = 0.f, a1 = 0.f;
        for (; t < t1; t += 2) {
            const int2 q0 = tbl[t];
            const int2 q1 = tbl[t + 1];
            const float c0 = __int_as_float(q0.x);
            const float c1 = __int_as_float(q1.x);
            a0 = fmaf(c0, *(const float*)(xl + q0.y),       a0);
            a1 = fmaf(c0, *(const float*)(xl + q0.y + 128), a1);
            a0 = fmaf(c1, *(const float*)(xl + q1.y),       a0);
            a1 = fmaf(c1, *(const float*)(xl + q1.y + 128), a1);
        }
        os[ro + lane]      = a0;
        os[ro + 32 + lane] = a1;
    }
    __syncthreads();

    stage_out(out, os, n0, npair, tid);
}

// ---------------- fallback: terms read straight from the param bank --------
__global__ void __launch_bounds__(NTHR, 2)
te_fall(const float* __restrict__ x, float* __restrict__ out, int nsamp,
        const __grid_constant__ Params2 P)
{
    extern __shared__ float sm[];
    float* xs = sm;
    float* os = sm + NAO2 * XST;

    const int tid = threadIdx.x;
    const int n0 = blockIdx.x * SPB;
    int valid = nsamp - n0; if (valid > SPB) valid = SPB;
    const int npair = valid * (NAO2 / 2);

    stage_in(x, xs, n0, npair, tid);
    __syncthreads();

    const int wid  = tid >> 5;
    const int lane = tid & 31;
    const char* xl = (const char*)(xs + lane);

    for (int i = wid; i < NAO2; i += NWARP) {
        int t  = P.tstart[i];
        const int t1 = P.tstart[i + 1];
        const int ro = P.rowoff[i];
        float a0 = 0.f, a1 = 0.f;
        for (; t < t1; t += 2) {
            const int2 q0 = P.term[t];
            const int2 q1 = P.term[t + 1];
            const float c0 = __int_as_float(q0.x);
            const float c1 = __int_as_float(q1.x);
            a0 = fmaf(c0, *(const float*)(xl + q0.y),       a0);
            a1 = fmaf(c0, *(const float*)(xl + q0.y + 128), a1);
            a0 = fmaf(c1, *(const float*)(xl + q1.y),       a0);
            a1 = fmaf(c1, *(const float*)(xl + q1.y + 128), a1);
        }
        os[ro + lane]      = a0;
        os[ro + 32 + lane] = a1;
    }
    __syncthreads();

    stage_out(out, os, n0, npair, tid);
}

// ===========================================================================
// Host-side construction of the CG / Wigner-3j sparse matrix (double prec).
// Runs only during the correctness call and graph capture — never timed.
// ===========================================================================
namespace cgbuild {

static double fct(int n) { double r = 1.0; for (int i = 2; i <= n; ++i) r *= i; return r; }

static double su2cg(int j1, int m1, int j2, int m2, int j3, int m3)
{
    if (m3 != m1 + m2) return 0.0;
    int vmin = std::max(std::max(-j1 + j2 + m3, -j1 + m1), 0);
    int vmax = std::min(std::min(j2 + j3 + m1, j3 - j1 + j2), j3 + m3);
    double c = std::sqrt((2.0 * j3 + 1) * fct(j3 + j1 - j2) * fct(j3 - j1 + j2) *
                         fct(j1 + j2 - j3) * fct(j3 + m3) * fct(j3 - m3) /
                         (fct(j1 + j2 + j3 + 1) * fct(j1 - m1) * fct(j1 + m1) *
                          fct(j2 - m2) * fct(j2 + m2)));
    double s = 0.0;
    for (int v = vmin; v <= vmax; ++v) {
        double sign = ((v + j2 + m2) & 1) ? -1.0 : 1.0;
        s += sign * fct(j2 + j3 + m1 - v) * fct(j1 - m1 + v) /
             (fct(v) * fct(j3 - j1 + j2 - v) * fct(j3 + m3 - v) * fct(v + j1 - j2 - m3));
    }
    return c * s;
}

typedef std::complex<double> C;

static std::vector<C> qmat(int l)
{
    int n = 2 * l + 1;
    std::vector<C> q((size_t)n * n, C(0, 0));
    const double is2 = 1.0 / std::sqrt(2.0);
    for (int m = -l; m < 0; ++m) {
        q[(size_t)(l + m) * n + (l - m)] = C(is2, 0);
        q[(size_t)(l + m) * n + (l + m)] = C(0, -is2);
    }
    q[(size_t)l * n + l] = C(1, 0);
    for (int m = 1; m <= l; ++m) {
        double sg = (m & 1) ? -1.0 : 1.0;
        q[(size_t)(l + m) * n + (l + m)] = C(sg * is2, 0);
        q[(size_t)(l + m) * n + (l - m)] = C(0, sg * is2);
    }
    C f(1, 0), mi(0, -1);
    for (int t = 0; t < l; ++t) f *= mi;
    for (auto& z : q) z *= f;
    return q;
}

static void wigner3j(int l1, int l2, int l3, double* outv)
{
    int n1 = 2 * l1 + 1, n2 = 2 * l2 + 1, n3 = 2 * l3 + 1;
    std::vector<double> csu2((size_t)n1 * n2 * n3, 0.0);
    for (int m1 = -l1; m1 <= l1; ++m1)
        for (int m2 = -l2; m2 <= l2; ++m2) {
            int m3 = m1 + m2;
            if (m3 >= -l3 && m3 <= l3)
                csu2[((size_t)(l1 + m1) * n2 + (l2 + m2)) * n3 + (l3 + m3)] =
                    su2cg(l1, m1, l2, m2, l3, m3);
        }
    std::vector<C> q1 = qmat(l1), q2 = qmat(l2), q3 = qmat(l3);
    std::vector<C> cc((size_t)n1 * n2 * n3, C(0, 0));
    for (int i = 0; i < n1; ++i)
        for (int k = 0; k < n2; ++k)
            for (int n = 0; n < n3; ++n) {
                double s = csu2[((size_t)i * n2 + k) * n3 + n];
                if (s == 0.0) continue;
                for (int a = 0; a < n1; ++a) {
                    C qa = q1[(size_t)i * n1 + a];
                    if (qa.real() == 0.0 && qa.imag() == 0.0) continue;
                    for (int b = 0; b < n2; ++b) {
                        C qab = qa * q2[(size_t)k * n2 + b] * s;
                        for (int c = 0; c < n3; ++c)
                            cc[((size_t)a * n2 + b) * n3 + c] += qab * std::conj(q3[(size_t)n * n3 + c]);
                    }
                }
            }
    double nre = 0, nim = 0;
    for (auto& z : cc) { nre += z.real() * z.real(); nim += z.imag() * z.imag(); }
    bool useRe = std::sqrt(nre) >= std::sqrt(nim);
    double nn  = std::sqrt(useRe ? nre : nim);
    for (size_t t = 0; t < cc.size(); ++t)
        outv[t] = (useRe ? cc[t].real() : cc[t].imag()) / nn;
}

static void build_params(Params2& P)
{
    memset(&P, 0, sizeof(P));
    const int LSh[6]    = {0, 0, 0, 1, 1, 2};
    const int IDXC[NAO] = {0, 1, 2, 5, 3, 4, 8, 6, 7, 11, 13, 9, 12, 10};
    int inv[NAO];
    for (int i = 0; i < NAO; ++i) inv[IDXC[i]] = i;

    struct Blk { int rs, nr, cs, nc, L, par; std::vector<double> cg; };
    std::vector<Blk> blks;
    int rs = 0;
    for (int a = 0; a < 6; ++a) {
        int li = LSh[a], nr = 2 * li + 1, cs = 0;
        for (int b = 0; b < 6; ++b) {
            int lj = LSh[b], nc = 2 * lj + 1;
            for (int L = std::abs(li - lj); L <= li + lj; ++L) {
                Blk bl; bl.rs = rs; bl.nr = nr; bl.cs = cs; bl.nc = nc; bl.L = L;
                bl.par = ((li + lj) & 1) ? -1 : 1;
                bl.cg.resize((size_t)(2 * L + 1) * nr * nc);
                wigner3j(L, li, lj, bl.cg.data());
                blks.push_back(std::move(bl));
            }
            cs += nc;
        }
        rs += nr;
    }

    // stable sort by (L, parity) — matches Python's stable `sorted`
    std::vector<int> perm(blks.size());
    std::iota(perm.begin(), perm.end(), 0);
    std::stable_sort(perm.begin(), perm.end(), [&](int i, int j) {
        if (blks[i].L != blks[j].L) return blks[i].L < blks[j].L;
        return blks[i].par < blks[j].par;
    });
    std::vector<int> outbase(blks.size());
    int base = 0;
    for (int idx : perm) { outbase[idx] = base; base += 2 * blks[idx].L + 1; }

    // per output-row list of (col-byte-offset, coef)
    std::vector<std::vector<std::pair<int, float>>> rows(NAO2);
    for (size_t bi = 0; bi < blks.size(); ++bi) {
        Blk& bl = blks[bi];
        int w = 2 * bl.L + 1;
        for (int k = 0; k < w; ++k) {
            int r = outbase[bi] + k;
            for (int i = 0; i < bl.nr; ++i)
                for (int j = 0; j < bl.nc; ++j) {
                    double v = bl.cg[((size_t)k * bl.nr + i) * bl.nc + j];
                    if (std::fabs(v) > 1e-9) {
                        int col = inv[bl.rs + i] * NAO + inv[bl.cs + j];
                        rows[r].push_back({col * XST * 4, (float)v});
                    }
                }
        }
    }

    // pad each row to an even term count
    for (auto& rr : rows)
        if (rr.size() & 1) rr.push_back({0, 0.0f});

    // sort rows by term count descending (stable) for warp load balance
    std::vector<int> order(NAO2);
    std::iota(order.begin(), order.end(), 0);
    std::stable_sort(order.begin(), order.end(), [&](int a, int b) {
        return rows[a].size() > rows[b].size();
    });

    int t = 0;
    for (int i = 0; i < NAO2; ++i) {
        int r = order[i];
        P.tstart[i] = t;
        P.rowoff[i] = r * XST;
        for (auto& pr : rows[r]) {
            if (t >= TABCAP) break;
            P.term[t].x = __builtin_bit_cast(int, pr.second);
            P.term[t].y = pr.first;
            ++t;
        }
    }
    for (int i = NAO2; i < 200; ++i) P.tstart[i] = t;
    P.ntab = t;
}

} // namespace cgbuild

extern "C" void kernel_launch(void* const* d_in, const int* in_sizes, int n_in,
                              void* d_out, int out_size)
{
    (void)n_in; (void)out_size;
    const float* x  = (const float*)d_in[0];
    float*      out = (float*)d_out;
    const int nsamp = in_sizes[0] / NAO2;

    Params2 P;
    cgbuild::build_params(P);

    const int grid = (nsamp + SPB - 1) / SPB;

    if (P.ntab <= TABSM) {
        cudaFuncSetAttribute(te_fast, cudaFuncAttributeMaxDynamicSharedMemorySize, SMEM_FAST);
        te_fast<<<grid, NTHR, SMEM_FAST>>>(x, out, nsamp, P);
    } else {
        cudaFuncSetAttribute(te_fall, cudaFuncAttributeMaxDynamicSharedMemorySize, SMEM_FALL);
        te_fall<<<grid, NTHR, SMEM_FALL>>>(x, out, nsamp, P);
    }
}

// round 7
// speedup vs baseline: 1.3895x; 1.3895x over previous
#include <cuda_runtime.h>

#define NAO   14
#define NAO2  196
#define SPB   64            // samples per block
#define XST   65            // smem word stride (odd -> conflict-free columns)
#define NTHR  512
#define NWARP 16
#define SMEM_BYTES (2 * NAO2 * XST * 4)

// ===========================================================================
// Compile-time construction of the CG / Wigner-3j sparse matrix.
// Everything below is evaluated by the compiler; the kernel sees only
// immediate constants.
// ===========================================================================
namespace ct {

constexpr double fct(int n) { double r = 1.0; for (int i = 2; i <= n; ++i) r *= i; return r; }

constexpr double csqrt(double v)
{
    if (v <= 0.0) return 0.0;
    double x = v < 1.0 ? 1.0 : v;
    for (int i = 0; i < 100; ++i) {
        double nx = 0.5 * (x + v / x);
        if (nx == x) break;
        x = nx;
    }
    return x;
}

constexpr double su2cg(int j1, int m1, int j2, int m2, int j3, int m3)
{
    if (m3 != m1 + m2) return 0.0;
    int vmin = -j1 + j2 + m3; if (-j1 + m1 > vmin) vmin = -j1 + m1; if (0 > vmin) vmin = 0;
    int vmax = j2 + j3 + m1; if (j3 - j1 + j2 < vmax) vmax = j3 - j1 + j2; if (j3 + m3 < vmax) vmax = j3 + m3;
    double c = csqrt((2.0 * j3 + 1) * fct(j3 + j1 - j2) * fct(j3 - j1 + j2) *
                     fct(j1 + j2 - j3) * fct(j3 + m3) * fct(j3 - m3) /
                     (fct(j1 + j2 + j3 + 1) * fct(j1 - m1) * fct(j1 + m1) *
                      fct(j2 - m2) * fct(j2 + m2)));
    double s = 0.0;
    for (int v = vmin; v <= vmax; ++v) {
        double sign = ((v + j2 + m2) & 1) ? -1.0 : 1.0;
        s += sign * fct(j2 + j3 + m1 - v) * fct(j1 - m1 + v) /
             (fct(v) * fct(j3 - j1 + j2 - v) * fct(j3 + m3 - v) * fct(v + j1 - j2 - m3));
    }
    return c * s;
}

struct CD { double re; double im; };
constexpr CD cmul(CD a, CD b) { return {a.re * b.re - a.im * b.im, a.re * b.im + a.im * b.re}; }
constexpr bool czero(CD a) { return a.re == 0.0 && a.im == 0.0; }

// q matrix for given l into q[(2l+1)^2], row-major [row][col]
constexpr void qmat(int l, CD* q)
{
    int n = 2 * l + 1;
    for (int i = 0; i < n * n; ++i) q[i] = {0.0, 0.0};
    double is2 = csqrt(0.5);
    for (int m = -l; m < 0; ++m) {
        q[(l + m) * n + (l - m)] = {is2, 0.0};    // col l+|m|
        q[(l + m) * n + (l + m)] = {0.0, -is2};   // col l-|m|
    }
    q[l * n + l] = {1.0, 0.0};
    for (int m = 1; m <= l; ++m) {
        double sg = (m & 1) ? -1.0 : 1.0;
        q[(l + m) * n + (l + m)] = {sg * is2, 0.0};
        q[(l + m) * n + (l - m)] = {0.0, sg * is2};
    }
    CD f{1.0, 0.0};
    const CD mi{0.0, -1.0};
    for (int t = 0; t < l; ++t) f = cmul(f, mi);
    for (int i = 0; i < n * n; ++i) q[i] = cmul(q[i], f);
}

constexpr void wigner3j(int l1, int l2, int l3, double* outv)
{
    const int n1 = 2 * l1 + 1, n2 = 2 * l2 + 1, n3 = 2 * l3 + 1;
    double csu2[225] = {};
    for (int m1 = -l1; m1 <= l1; ++m1)
        for (int m2 = -l2; m2 <= l2; ++m2) {
            int m3 = m1 + m2;
            if (m3 >= -l3 && m3 <= l3)
                csu2[((l1 + m1) * n2 + (l2 + m2)) * n3 + (l3 + m3)] =
                    su2cg(l1, m1, l2, m2, l3, m3);
        }
    CD q1[81] = {}, q2[25] = {}, q3[25] = {};
    qmat(l1, q1); qmat(l2, q2); qmat(l3, q3);

    CD cc[225] = {};
    for (int i = 0; i < n1 * n2 * n3; ++i) cc[i] = {0.0, 0.0};
    // cc[a][b][c] = sum_{i,k,n} q1[i][a] q2[k][b] conj(q3[n][c]) csu2[i][k][n]
    for (int i = 0; i < n1; ++i)
        for (int k = 0; k < n2; ++k)
            for (int n = 0; n < n3; ++n) {
                double s = csu2[(i * n2 + k) * n3 + n];
                if (s == 0.0) continue;
                for (int a = 0; a < n1; ++a) {
                    CD qa = q1[i * n1 + a];
                    if (czero(qa)) continue;
                    for (int b = 0; b < n2; ++b) {
                        CD qb = q2[k * n2 + b];
                        if (czero(qb)) continue;
                        CD qab = cmul(qa, qb);
                        qab.re *= s; qab.im *= s;
                        for (int c = 0; c < n3; ++c) {
                            CD q3c = q3[n * n3 + c];
                            if (czero(q3c)) continue;
                            CD cj{q3c.re, -q3c.im};
                            CD add = cmul(qab, cj);
                            cc[(a * n2 + b) * n3 + c].re += add.re;
                            cc[(a * n2 + b) * n3 + c].im += add.im;
                        }
                    }
                }
            }
    double nre = 0.0, nim = 0.0;
    for (int i = 0; i < n1 * n2 * n3; ++i) {
        nre += cc[i].re * cc[i].re;
        nim += cc[i].im * cc[i].im;
    }
    bool useRe = csqrt(nre) >= csqrt(nim);
    double nn = csqrt(useRe ? nre : nim);
    for (int i = 0; i < n1 * n2 * n3; ++i)
        outv[i] = (useRe ? cc[i].re : cc[i].im) / nn;
}

struct CTab {
    float coef[2200];
    int   off[2200];      // word offset into xs: col * XST
    int   tst[197];       // per natural output row
    int   wrows[16][16];  // warp -> row list (balanced)
    int   nwr[16];
};

constexpr CTab build()
{
    CTab T{};
    const int LSh[6]  = {0, 0, 0, 1, 1, 2};
    const int IDXC[NAO] = {0, 1, 2, 5, 3, 4, 8, 6, 7, 11, 13, 9, 12, 10};
    int inv[NAO] = {};
    for (int i = 0; i < NAO; ++i) inv[IDXC[i]] = i;

    // enumerate blocks
    int brs[56] = {}, bnr[56] = {}, bcs[56] = {}, bnc[56] = {}, bL[56] = {}, bpar[56] = {}, bco[56] = {};
    double cg[2120] = {};
    int nb = 0, cgo = 0, rs = 0;
    for (int a = 0; a < 6; ++a) {
        int li = LSh[a], nr = 2 * li + 1, cs = 0;
        for (int b = 0; b < 6; ++b) {
            int lj = LSh[b], nc = 2 * lj + 1;
            int L0 = li > lj ? li - lj : lj - li;
            for (int L = L0; L <= li + lj; ++L) {
                brs[nb] = rs; bnr[nb] = nr; bcs[nb] = cs; bnc[nb] = nc;
                bL[nb] = L; bpar[nb] = ((li + lj) & 1) ? -1 : 1; bco[nb] = cgo;
                wigner3j(L, li, lj, &cg[cgo]);
                cgo += (2 * L + 1) * nr * nc;
                ++nb;
            }
            cs += nc;
        }
        rs += nr;
    }

    // stable sort of blocks by (L, parity) -> output layout
    int perm[56] = {};
    for (int i = 0; i < 56; ++i) perm[i] = i;
    for (int i = 1; i < 56; ++i) {
        int p = perm[i]; int j = i - 1;
        while (j >= 0 && (bL[perm[j]] > bL[p] ||
               (bL[perm[j]] == bL[p] && bpar[perm[j]] > bpar[p]))) {
            perm[j + 1] = perm[j]; --j;
        }
        perm[j + 1] = p;
    }
    int outbase[56] = {};
    { int base = 0; for (int t = 0; t < 56; ++t) { outbase[perm[t]] = base; base += 2 * bL[perm[t]] + 1; } }

    // per-row term lists
    float rc[196][26] = {};
    int   ro[196][26] = {};
    int   rn[196] = {};
    for (int bi = 0; bi < nb; ++bi) {
        int w = 2 * bL[bi] + 1;
        for (int k = 0; k < w; ++k) {
            int r = outbase[bi] + k;
            for (int i = 0; i < bnr[bi]; ++i)
                for (int j = 0; j < bnc[bi]; ++j) {
                    double v = cg[bco[bi] + (k * bnr[bi] + i) * bnc[bi] + j];
                    double av = v < 0 ? -v : v;
                    if (av > 1e-9) {
                        int col = inv[brs[bi] + i] * NAO + inv[bcs[bi] + j];
                        rc[r][rn[r]] = (float)v;
                        ro[r][rn[r]] = col * XST;
                        rn[r]++;
                    }
                }
        }
    }

    // flatten term table in natural row order
    {
        int t = 0;
        for (int r = 0; r < NAO2; ++r) {
            T.tst[r] = t;
            for (int q = 0; q < rn[r]; ++q) { T.coef[t] = rc[r][q]; T.off[t] = ro[r][q]; ++t; }
        }
        T.tst[NAO2] = t;
    }

    // balance rows across 16 warps: sort rows by nnz desc (stable), greedy min-cost
    int order[196] = {};
    for (int i = 0; i < 196; ++i) order[i] = i;
    for (int i = 1; i < 196; ++i) {
        int p = order[i]; int j = i - 1;
        while (j >= 0 && rn[order[j]] < rn[p]) { order[j + 1] = order[j]; --j; }
        order[j + 1] = p;
    }
    int wcost[16] = {};
    for (int i = 0; i < 196; ++i) {
        int best = 0;
        for (int w = 1; w < 16; ++w) if (wcost[w] < wcost[best]) best = w;
        T.wrows[best][T.nwr[best]] = order[i];
        T.nwr[best]++;
        wcost[best] += rn[order[i]] + 2;
    }
    return T;
}

constexpr CTab TAB = build();

} // namespace ct

// ===========================================================================
// Fully-unrolled compute: immediate coefficients, immediate LDS offsets.
// ===========================================================================
template<int T, int TEND>
__device__ __forceinline__ void terms_run(const float* xl, float& a0, float& a1)
{
    constexpr float c = ct::TAB.coef[T];
    constexpr int   o = ct::TAB.off[T];
    a0 = fmaf(c, xl[o],      a0);
    a1 = fmaf(c, xl[o + 32], a1);
    if constexpr (T + 1 < TEND) terms_run<T + 1, TEND>(xl, a0, a1);
}

template<int W, int I>
__device__ __forceinline__ void rows_run(const float* xl, float* os, int lane)
{
    constexpr int r  = ct::TAB.wrows[W][I];
    constexpr int t0 = ct::TAB.tst[r];
    constexpr int t1 = ct::TAB.tst[r + 1];
    float a0 = 0.f, a1 = 0.f;
    if constexpr (t1 > t0) terms_run<t0, t1>(xl, a0, a1);
    os[r * XST + lane]      = a0;
    os[r * XST + 32 + lane] = a1;
    if constexpr (I + 1 < ct::TAB.nwr[W]) rows_run<W, I + 1>(xl, os, lane);
}

__global__ void __launch_bounds__(NTHR, 2)
te_kernel(const float* __restrict__ x, float* __restrict__ out, int nsamp)
{
    extern __shared__ float sm[];
    float* xs = sm;                  // [196][65]  element-major, sample fastest
    float* os = sm + NAO2 * XST;     // [196][65]

    const int tid = threadIdx.x;
    const int n0  = blockIdx.x * SPB;
    int valid = nsamp - n0; if (valid > SPB) valid = SPB;
    const int npair = valid * (NAO2 / 2);

    // ---- stage in: float2 global reads, 2x STS ----
    {
        const float2* src = (const float2*)(x + (long long)n0 * NAO2);
        int s = tid / 98, e2 = tid - s * 98;
        #pragma unroll 2
        for (int f = tid; f < npair; f += NTHR) {
            float2 v = src[f];
            int w = (2 * e2) * XST + s;
            xs[w]       = v.x;
            xs[w + XST] = v.y;
            e2 += 22; s += 5;
            if (e2 >= 98) { e2 -= 98; s += 1; }
        }
    }
    __syncthreads();

    // ---- fully-unrolled sparse matvec, warp-specialized row sets ----
    {
        const int wid  = tid >> 5;
        const int lane = tid & 31;
        const float* xl = xs + lane;
        switch (wid) {
            case 0:  rows_run<0,  0>(xl, os, lane); break;
            case 1:  rows_run<1,  0>(xl, os, lane); break;
            case 2:  rows_run<2,  0>(xl, os, lane); break;
            case 3:  rows_run<3,  0>(xl, os, lane); break;
            case 4:  rows_run<4,  0>(xl, os, lane); break;
            case 5:  rows_run<5,  0>(xl, os, lane); break;
            case 6:  rows_run<6,  0>(xl, os, lane); break;
            case 7:  rows_run<7,  0>(xl, os, lane); break;
            case 8:  rows_run<8,  0>(xl, os, lane); break;
            case 9:  rows_run<9,  0>(xl, os, lane); break;
            case 10: rows_run<10, 0>(xl, os, lane); break;
            case 11: rows_run<11, 0>(xl, os, lane); break;
            case 12: rows_run<12, 0>(xl, os, lane); break;
            case 13: rows_run<13, 0>(xl, os, lane); break;
            case 14: rows_run<14, 0>(xl, os, lane); break;
            default: rows_run<15, 0>(xl, os, lane); break;
        }
    }
    __syncthreads();

    // ---- stage out: 2x LDS, float2 global writes ----
    {
        float2* dst = (float2*)(out + (long long)n0 * NAO2);
        int s = tid / 98, e2 = tid - s * 98;
        #pragma unroll 2
        for (int f = tid; f < npair; f += NTHR) {
            int w = (2 * e2) * XST + s;
            float2 v;
            v.x = os[w];
            v.y = os[w + XST];
            dst[f] = v;
            e2 += 22; s += 5;
            if (e2 >= 98) { e2 -= 98; s += 1; }
        }
    }
}

extern "C" void kernel_launch(void* const* d_in, const int* in_sizes, int n_in,
                              void* d_out, int out_size)
{
    (void)n_in; (void)out_size;
    const float* x  = (const float*)d_in[0];
    float*      out = (float*)d_out;
    const int nsamp = in_sizes[0] / NAO2;

    cudaFuncSetAttribute(te_kernel, cudaFuncAttributeMaxDynamicSharedMemorySize, SMEM_BYTES);

    const int grid = (nsamp + SPB - 1) / SPB;
    te_kernel<<<grid, NTHR, SMEM_BYTES>>>(x, out, nsamp);
}

// round 9
// speedup vs baseline: 1.5319x; 1.1024x over previous
#include <cuda_runtime.h>

#define NAO   14
#define NAO2  196
#define SPB   32            // samples per block
#define XST   33            // smem word stride (odd -> conflict-free columns)
#define NTHR  256
#define NWARP 8
#define SMEM_BYTES (2 * NAO2 * XST * 4)

// ===========================================================================
// Compile-time construction of the CG / Wigner-3j sparse matrix.
// Everything below is evaluated by the compiler; the kernel sees only
// immediate constants.
// ===========================================================================
namespace ct {

constexpr double fct(int n) { double r = 1.0; for (int i = 2; i <= n; ++i) r *= i; return r; }

constexpr double csqrt(double v)
{
    if (v <= 0.0) return 0.0;
    double x = v < 1.0 ? 1.0 : v;
    for (int i = 0; i < 100; ++i) {
        double nx = 0.5 * (x + v / x);
        if (nx == x) break;
        x = nx;
    }
    return x;
}

constexpr double su2cg(int j1, int m1, int j2, int m2, int j3, int m3)
{
    if (m3 != m1 + m2) return 0.0;
    int vmin = -j1 + j2 + m3; if (-j1 + m1 > vmin) vmin = -j1 + m1; if (0 > vmin) vmin = 0;
    int vmax = j2 + j3 + m1; if (j3 - j1 + j2 < vmax) vmax = j3 - j1 + j2; if (j3 + m3 < vmax) vmax = j3 + m3;
    double c = csqrt((2.0 * j3 + 1) * fct(j3 + j1 - j2) * fct(j3 - j1 + j2) *
                     fct(j1 + j2 - j3) * fct(j3 + m3) * fct(j3 - m3) /
                     (fct(j1 + j2 + j3 + 1) * fct(j1 - m1) * fct(j1 + m1) *
                      fct(j2 - m2) * fct(j2 + m2)));
    double s = 0.0;
    for (int v = vmin; v <= vmax; ++v) {
        double sign = ((v + j2 + m2) & 1) ? -1.0 : 1.0;
        s += sign * fct(j2 + j3 + m1 - v) * fct(j1 - m1 + v) /
             (fct(v) * fct(j3 - j1 + j2 - v) * fct(j3 + m3 - v) * fct(v + j1 - j2 - m3));
    }
    return c * s;
}

struct CD { double re; double im; };
constexpr CD cmul(CD a, CD b) { return {a.re * b.re - a.im * b.im, a.re * b.im + a.im * b.re}; }
constexpr bool czero(CD a) { return a.re == 0.0 && a.im == 0.0; }

constexpr void qmat(int l, CD* q)
{
    int n = 2 * l + 1;
    for (int i = 0; i < n * n; ++i) q[i] = {0.0, 0.0};
    double is2 = csqrt(0.5);
    for (int m = -l; m < 0; ++m) {
        q[(l + m) * n + (l - m)] = {is2, 0.0};
        q[(l + m) * n + (l + m)] = {0.0, -is2};
    }
    q[l * n + l] = {1.0, 0.0};
    for (int m = 1; m <= l; ++m) {
        double sg = (m & 1) ? -1.0 : 1.0;
        q[(l + m) * n + (l + m)] = {sg * is2, 0.0};
        q[(l + m) * n + (l - m)] = {0.0, sg * is2};
    }
    CD f{1.0, 0.0};
    const CD mi{0.0, -1.0};
    for (int t = 0; t < l; ++t) f = cmul(f, mi);
    for (int i = 0; i < n * n; ++i) q[i] = cmul(q[i], f);
}

constexpr void wigner3j(int l1, int l2, int l3, double* outv)
{
    const int n1 = 2 * l1 + 1, n2 = 2 * l2 + 1, n3 = 2 * l3 + 1;
    double csu2[225] = {};
    for (int m1 = -l1; m1 <= l1; ++m1)
        for (int m2 = -l2; m2 <= l2; ++m2) {
            int m3 = m1 + m2;
            if (m3 >= -l3 && m3 <= l3)
                csu2[((l1 + m1) * n2 + (l2 + m2)) * n3 + (l3 + m3)] =
                    su2cg(l1, m1, l2, m2, l3, m3);
        }
    CD q1[81] = {}, q2[25] = {}, q3[25] = {};
    qmat(l1, q1); qmat(l2, q2); qmat(l3, q3);

    CD cc[225] = {};
    for (int i = 0; i < n1 * n2 * n3; ++i) cc[i] = {0.0, 0.0};
    for (int i = 0; i < n1; ++i)
        for (int k = 0; k < n2; ++k)
            for (int n = 0; n < n3; ++n) {
                double s = csu2[(i * n2 + k) * n3 + n];
                if (s == 0.0) continue;
                for (int a = 0; a < n1; ++a) {
                    CD qa = q1[i * n1 + a];
                    if (czero(qa)) continue;
                    for (int b = 0; b < n2; ++b) {
                        CD qb = q2[k * n2 + b];
                        if (czero(qb)) continue;
                        CD qab = cmul(qa, qb);
                        qab.re *= s; qab.im *= s;
                        for (int c = 0; c < n3; ++c) {
                            CD q3c = q3[n * n3 + c];
                            if (czero(q3c)) continue;
                            CD cj{q3c.re, -q3c.im};
                            CD add = cmul(qab, cj);
                            cc[(a * n2 + b) * n3 + c].re += add.re;
                            cc[(a * n2 + b) * n3 + c].im += add.im;
                        }
                    }
                }
            }
    double nre = 0.0, nim = 0.0;
    for (int i = 0; i < n1 * n2 * n3; ++i) {
        nre += cc[i].re * cc[i].re;
        nim += cc[i].im * cc[i].im;
    }
    bool useRe = csqrt(nre) >= csqrt(nim);
    double nn = csqrt(useRe ? nre : nim);
    for (int i = 0; i < n1 * n2 * n3; ++i)
        outv[i] = (useRe ? cc[i].re : cc[i].im) / nn;
}

struct CTab {
    float coef[2200];
    int   off[2200];        // word offset into xs: col * XST
    int   tst[197];         // per natural output row
    int   wrows[NWARP][64]; // warp -> row list (balanced)
    int   nwr[NWARP];
};

constexpr CTab build()
{
    CTab T{};
    const int LSh[6]  = {0, 0, 0, 1, 1, 2};
    const int IDXC[NAO] = {0, 1, 2, 5, 3, 4, 8, 6, 7, 11, 13, 9, 12, 10};
    int inv[NAO] = {};
    for (int i = 0; i < NAO; ++i) inv[IDXC[i]] = i;

    // enumerate blocks
    int brs[56] = {}, bnr[56] = {}, bcs[56] = {}, bnc[56] = {}, bL[56] = {}, bpar[56] = {}, bco[56] = {};
    double cg[2120] = {};
    int nb = 0, cgo = 0, rs = 0;
    for (int a = 0; a < 6; ++a) {
        int li = LSh[a], nr = 2 * li + 1, cs = 0;
        for (int b = 0; b < 6; ++b) {
            int lj = LSh[b], nc = 2 * lj + 1;
            int L0 = li > lj ? li - lj : lj - li;
            for (int L = L0; L <= li + lj; ++L) {
                brs[nb] = rs; bnr[nb] = nr; bcs[nb] = cs; bnc[nb] = nc;
                bL[nb] = L; bpar[nb] = ((li + lj) & 1) ? -1 : 1; bco[nb] = cgo;
                wigner3j(L, li, lj, &cg[cgo]);
                cgo += (2 * L + 1) * nr * nc;
                ++nb;
            }
            cs += nc;
        }
        rs += nr;
    }

    // stable sort of blocks by (L, parity) -> output layout
    int perm[56] = {};
    for (int i = 0; i < 56; ++i) perm[i] = i;
    for (int i = 1; i < 56; ++i) {
        int p = perm[i]; int j = i - 1;
        while (j >= 0 && (bL[perm[j]] > bL[p] ||
               (bL[perm[j]] == bL[p] && bpar[perm[j]] > bpar[p]))) {
            perm[j + 1] = perm[j]; --j;
        }
        perm[j + 1] = p;
    }
    int outbase[56] = {};
    { int base = 0; for (int t = 0; t < 56; ++t) { outbase[perm[t]] = base; base += 2 * bL[perm[t]] + 1; } }

    // per-row term lists
    float rc[196][26] = {};
    int   ro[196][26] = {};
    int   rn[196] = {};
    for (int bi = 0; bi < nb; ++bi) {
        int w = 2 * bL[bi] + 1;
        for (int k = 0; k < w; ++k) {
            int r = outbase[bi] + k;
            for (int i = 0; i < bnr[bi]; ++i)
                for (int j = 0; j < bnc[bi]; ++j) {
                    double v = cg[bco[bi] + (k * bnr[bi] + i) * bnc[bi] + j];
                    double av = v < 0 ? -v : v;
                    if (av > 1e-9) {
                        int col = inv[brs[bi] + i] * NAO + inv[bcs[bi] + j];
                        rc[r][rn[r]] = (float)v;
                        ro[r][rn[r]] = col * XST;
                        rn[r]++;
                    }
                }
        }
    }

    // flatten term table in natural row order
    {
        int t = 0;
        for (int r = 0; r < NAO2; ++r) {
            T.tst[r] = t;
            for (int q = 0; q < rn[r]; ++q) { T.coef[t] = rc[r][q]; T.off[t] = ro[r][q]; ++t; }
        }
        T.tst[NAO2] = t;
    }

    // balance rows across warps: sort rows by nnz desc (stable), greedy min-cost
    int order[196] = {};
    for (int i = 0; i < 196; ++i) order[i] = i;
    for (int i = 1; i < 196; ++i) {
        int p = order[i]; int j = i - 1;
        while (j >= 0 && rn[order[j]] < rn[p]) { order[j + 1] = order[j]; --j; }
        order[j + 1] = p;
    }
    int wcost[NWARP] = {};
    for (int i = 0; i < 196; ++i) {
        int best = 0;
        for (int w = 1; w < NWARP; ++w) if (wcost[w] < wcost[best]) best = w;
        T.wrows[best][T.nwr[best]] = order[i];
        T.nwr[best]++;
        wcost[best] += rn[order[i]] + 2;
    }
    return T;
}

constexpr CTab TAB = build();

} // namespace ct

// ===========================================================================
// Fully-unrolled compute: immediate coefficients, immediate LDS offsets.
// ===========================================================================
template<int T, int TEND>
__device__ __forceinline__ void terms_run(const float* xl, float& a0)
{
    constexpr float c = ct::TAB.coef[T];
    constexpr int   o = ct::TAB.off[T];
    a0 = fmaf(c, xl[o], a0);
    if constexpr (T + 1 < TEND) terms_run<T + 1, TEND>(xl, a0);
}

template<int W, int I>
__device__ __forceinline__ void rows_run(const float* xl, float* os, int lane)
{
    constexpr int r  = ct::TAB.wrows[W][I];
    constexpr int t0 = ct::TAB.tst[r];
    constexpr int t1 = ct::TAB.tst[r + 1];
    float a0 = 0.f;
    if constexpr (t1 > t0) terms_run<t0, t1>(xl, a0);
    os[r * XST + lane] = a0;
    if constexpr (I + 1 < ct::TAB.nwr[W]) rows_run<W, I + 1>(xl, os, lane);
}

__global__ void __launch_bounds__(NTHR, 4)
te_kernel(const float* __restrict__ x, float* __restrict__ out, int nsamp)
{
    extern __shared__ float sm[];
    float* xs = sm;                  // [196][33]  element-major, sample fastest
    float* os = sm + NAO2 * XST;     // [196][33]

    const int tid = threadIdx.x;
    const int n0  = blockIdx.x * SPB;
    int valid = nsamp - n0; if (valid > SPB) valid = SPB;
    const int npair = valid * (NAO2 / 2);

    // ---- stage in: float2 global reads, 2x STS (2-way conflict) ----
    {
        const float2* src = (const float2*)(x + (long long)n0 * NAO2);
        int s = tid / 98, e2 = tid - (tid / 98) * 98;
        #pragma unroll 2
        for (int f = tid; f < npair; f += NTHR) {
            float2 v = src[f];
            int w = (2 * e2) * XST + s;
            xs[w]       = v.x;
            xs[w + XST] = v.y;
            e2 += 60; s += 2;                       // 256 = 2*98 + 60
            if (e2 >= 98) { e2 -= 98; s += 1; }
        }
    }
    __syncthreads();

    // ---- fully-unrolled sparse matvec, warp-specialized row sets ----
    {
        const int wid  = tid >> 5;
        const int lane = tid & 31;
        const float* xl = xs + lane;
        switch (wid) {
            case 0:  rows_run<0, 0>(xl, os, lane); break;
            case 1:  rows_run<1, 0>(xl, os, lane); break;
            case 2:  rows_run<2, 0>(xl, os, lane); break;
            case 3:  rows_run<3, 0>(xl, os, lane); break;
            case 4:  rows_run<4, 0>(xl, os, lane); break;
            case 5:  rows_run<5, 0>(xl, os, lane); break;
            case 6:  rows_run<6, 0>(xl, os, lane); break;
            default: rows_run<7, 0>(xl, os, lane); break;
        }
    }
    __syncthreads();

    // ---- stage out: 2x LDS, float2 global writes ----
    {
        float2* dst = (float2*)(out + (long long)n0 * NAO2);
        int s = tid / 98, e2 = tid - (tid / 98) * 98;
        #pragma unroll 2
        for (int f = tid; f < npair; f += NTHR) {
            int w = (2 * e2) * XST + s;
            float2 v;
            v.x = os[w];
            v.y = os[w + XST];
            dst[f] = v;
            e2 += 60; s += 2;
            if (e2 >= 98) { e2 -= 98; s += 1; }
        }
    }
}

extern "C" void kernel_launch(void* const* d_in, const int* in_sizes, int n_in,
                              void* d_out, int out_size)
{
    (void)n_in; (void)out_size;
    const float* x  = (const float*)d_in[0];
    float*      out = (float*)d_out;
    const int nsamp = in_sizes[0] / NAO2;

    cudaFuncSetAttribute(te_kernel, cudaFuncAttributeMaxDynamicSharedMemorySize, SMEM_BYTES);

    const int grid = (nsamp + SPB - 1) / SPB;
    te_kernel<<<grid, NTHR, SMEM_BYTES>>>(x, out, nsamp);
}